// round 15
// baseline (speedup 1.0000x reference)
#include <cuda_runtime.h>
#include <cuda_bf16.h>
#include <cstdint>

#define BB 20
#define SS 4096
#define EE 256
#define NB 32
#define BLK 128
#define CTX 384

// SMEM padded row stride in bytes (32 bf16 = 64B data + 16B pad, 16B-aligned rows)
#define SSTRIDE 80
// one buffer = Ah | Al | Bh | Bl, each 128*SSTRIDE = 10240 B
#define BUF_AH 0
#define BUF_AL 10240
#define BUF_BH 20480
#define BUF_BL 30720
#define BUF_SZ 40960
#define SMEM_PIPE (2 * BUF_SZ)  // 81920 B dynamic

// ---------------- device scratch ----------------
__device__ float g_qm[(size_t)BB * SS * EE];             // x @ (Wq Wk^T / 16)
__device__ float g_uT[(size_t)BB * EE * SS];             // (x @ Wv Wo) transposed [b][e][seq]
__device__ float g_probs[(size_t)BB * NB * BLK * CTX];   // exp(logits), unnormalized
__device__ float g_rinv[BB * NB * BLK];                  // 1/rowsum
__device__ __nv_bfloat16 g_mth[2][EE * EE];              // folded weights^T hi (0:M 1:U)
__device__ __nv_bfloat16 g_mtl[2][EE * EE];              // folded weights^T lo

// ---------------- PTX primitives ----------------
static __device__ __forceinline__ uint32_t smem_u32(const void* p) {
    return (uint32_t)__cvta_generic_to_shared(p);
}
static __device__ __forceinline__ void ldsm4(uint32_t& r0, uint32_t& r1, uint32_t& r2,
                                             uint32_t& r3, uint32_t addr) {
    asm volatile("ldmatrix.sync.aligned.m8n8.x4.shared.b16 {%0,%1,%2,%3}, [%4];"
                 : "=r"(r0), "=r"(r1), "=r"(r2), "=r"(r3) : "r"(addr));
}
static __device__ __forceinline__ void mma16816(float* c, const uint32_t* a, const uint32_t* b) {
    asm volatile(
        "mma.sync.aligned.m16n8k16.row.col.f32.bf16.bf16.f32 "
        "{%0,%1,%2,%3}, {%4,%5,%6,%7}, {%8,%9}, {%0,%1,%2,%3};"
        : "+f"(c[0]), "+f"(c[1]), "+f"(c[2]), "+f"(c[3])
        : "r"(a[0]), "r"(a[1]), "r"(a[2]), "r"(a[3]), "r"(b[0]), "r"(b[1]));
}

// ---------------- register staging: LDG early, convert+STS late ----------------
struct StageCvt { float4 v[4]; };
static __device__ __forceinline__ void ldg_cvt(StageCvt& st, const float* __restrict__ src,
                                               int lda, int tid) {
#pragma unroll
    for (int i = 0; i < 4; i++) {
        int f = tid + 256 * i;
        int row = f >> 3, c4 = f & 7;
        st.v[i] = *(const float4*)(src + (size_t)row * lda + c4 * 4);
    }
}
static __device__ __forceinline__ void sts_cvt(const StageCvt& st, char* shi, char* slo,
                                               int tid) {
#pragma unroll
    for (int i = 0; i < 4; i++) {
        int f = tid + 256 * i;
        int row = f >> 3, c4 = f & 7;
        float4 v = st.v[i];
        __nv_bfloat162 ha = __floats2bfloat162_rn(v.x, v.y);
        __nv_bfloat162 hb = __floats2bfloat162_rn(v.z, v.w);
        float2 fa = __bfloat1622float2(ha);
        float2 fb = __bfloat1622float2(hb);
        __nv_bfloat162 la = __floats2bfloat162_rn(v.x - fa.x, v.y - fa.y);
        __nv_bfloat162 lb = __floats2bfloat162_rn(v.z - fb.x, v.w - fb.y);
        int off = row * SSTRIDE + c4 * 8;
        *(uint2*)(shi + off) = make_uint2(*(uint32_t*)&ha, *(uint32_t*)&hb);
        *(uint2*)(slo + off) = make_uint2(*(uint32_t*)&la, *(uint32_t*)&lb);
    }
}
struct StageW { uint4 v[2][2]; };  // [i][0]=hi [i][1]=lo
static __device__ __forceinline__ void ldg_w(StageW& st, const __nv_bfloat16* __restrict__ wh,
                                             const __nv_bfloat16* __restrict__ wl, int tid) {
#pragma unroll
    for (int i = 0; i < 2; i++) {
        int f = tid + 256 * i;
        int row = f >> 2, c = f & 3;
        st.v[i][0] = *(const uint4*)(wh + (size_t)row * EE + c * 8);
        st.v[i][1] = *(const uint4*)(wl + (size_t)row * EE + c * 8);
    }
}
static __device__ __forceinline__ void sts_w(const StageW& st, char* shi, char* slo, int tid) {
#pragma unroll
    for (int i = 0; i < 2; i++) {
        int f = tid + 256 * i;
        int row = f >> 2, c = f & 3;
        int off = row * SSTRIDE + c * 16;
        *(uint4*)(shi + off) = st.v[i][0];
        *(uint4*)(slo + off) = st.v[i][1];
    }
}

// ---------------- one 32-k chunk of bf16x3 MMAs from buffer `base` ----------------
static __device__ __forceinline__ void mma_chunk(uint32_t base, int lane, int m_warp,
                                                 int n_warp, float c[2][8][4]) {
    const uint32_t uAh = base + BUF_AH, uAl = base + BUF_AL;
    const uint32_t uBh = base + BUF_BH, uBl = base + BUF_BL;
#pragma unroll
    for (int kk = 0; kk < 2; kk++) {
        const int kb = kk * 32;
        uint32_t ah[2][4], al[2][4], bh[8][2], bl[8][2];
        const uint32_t a_off =
            (uint32_t)((m_warp + (lane & 15)) * SSTRIDE + kb + ((lane >> 4) << 4));
        ldsm4(ah[0][0], ah[0][1], ah[0][2], ah[0][3], uAh + a_off);
        ldsm4(ah[1][0], ah[1][1], ah[1][2], ah[1][3], uAh + a_off + 16 * SSTRIDE);
        ldsm4(al[0][0], al[0][1], al[0][2], al[0][3], uAl + a_off);
        ldsm4(al[1][0], al[1][1], al[1][2], al[1][3], uAl + a_off + 16 * SSTRIDE);
        const int br = (lane & 7) + ((lane >> 4) << 3);
        const int bc = kb + (((lane >> 3) & 1) << 4);
#pragma unroll
        for (int j = 0; j < 4; j++) {
            const uint32_t b_off = (uint32_t)((n_warp + 16 * j + br) * SSTRIDE + bc);
            uint32_t r0, r1, r2, r3;
            ldsm4(r0, r1, r2, r3, uBh + b_off);
            bh[2 * j][0] = r0; bh[2 * j][1] = r1;
            bh[2 * j + 1][0] = r2; bh[2 * j + 1][1] = r3;
            ldsm4(r0, r1, r2, r3, uBl + b_off);
            bl[2 * j][0] = r0; bl[2 * j][1] = r1;
            bl[2 * j + 1][0] = r2; bl[2 * j + 1][1] = r3;
        }
#pragma unroll
        for (int mi = 0; mi < 2; mi++)
#pragma unroll
            for (int nj = 0; nj < 8; nj++) {
                mma16816(c[mi][nj], ah[mi], bh[nj]);
                mma16816(c[mi][nj], ah[mi], bl[nj]);
                mma16816(c[mi][nj], al[mi], bh[nj]);
            }
    }
}

// ---------------- folded-weight prep ----------------
// M^T[n,k] = (Wq Wk^T)[k,n]/16 = sum_e Wq[k,e]*Wk[n,e]/16
// U^T[n,k] = (Wv Wo)[k,n]    = sum_e Wv[k,e]*Wo[e,n]
__global__ __launch_bounds__(256) void prep_mu(const float* __restrict__ Wq,
                                               const float* __restrict__ Wk,
                                               const float* __restrict__ Wv,
                                               const float* __restrict__ Wo) {
    int idx = blockIdx.x * 256 + threadIdx.x;  // 131072 total
    int mat = idx >> 16;
    int n = (idx >> 8) & 255, k = idx & 255;
    float s = 0.f;
    if (mat == 0) {
        for (int e = 0; e < EE; e++) s += Wq[k * EE + e] * Wk[n * EE + e];
        s *= 0.0625f;
    } else {
        for (int e = 0; e < EE; e++) s += Wv[k * EE + e] * Wo[e * EE + n];
    }
    __nv_bfloat16 h = __float2bfloat16_rn(s);
    g_mth[mat][n * EE + k] = h;
    g_mtl[mat][n * EE + k] = __float2bfloat16_rn(s - __bfloat162float(h));
}

// ---------------- projections: qm = x@M, u = x@U (u stored transposed). grid (640,4) ----------------
__global__ __launch_bounds__(256) void proj_mma(const float* __restrict__ x) {
    extern __shared__ __align__(16) char dsm[];
    const int tid = threadIdx.x, lane = tid & 31, wid = tid >> 5;
    const int m_warp = (wid >> 1) * 32, n_warp = (wid & 1) * 64;
    const int m0 = blockIdx.x * 128;
    const int sel = blockIdx.y >> 1, nh = blockIdx.y & 1;
    const __nv_bfloat16* wh = g_mth[sel] + (size_t)nh * 128 * EE;
    const __nv_bfloat16* wl = g_mtl[sel] + (size_t)nh * 128 * EE;
    const float* asrc = x + (size_t)m0 * EE;
    char* buf[2] = {dsm, dsm + BUF_SZ};
    const uint32_t ub[2] = {smem_u32(buf[0]), smem_u32(buf[1])};

    float c[2][8][4];
#pragma unroll
    for (int i = 0; i < 2; i++)
#pragma unroll
        for (int j = 0; j < 8; j++)
#pragma unroll
            for (int t = 0; t < 4; t++) c[i][j][t] = 0.f;

    StageCvt sa; StageW sw;
    ldg_cvt(sa, asrc, EE, tid);
    ldg_w(sw, wh, wl, tid);
    sts_cvt(sa, buf[0] + BUF_AH, buf[0] + BUF_AL, tid);
    sts_w(sw, buf[0] + BUF_BH, buf[0] + BUF_BL, tid);
    __syncthreads();
    for (int kc = 0; kc < 8; kc++) {
        int cur = kc & 1, nxt = cur ^ 1;
        if (kc < 7) {
            ldg_cvt(sa, asrc + (kc + 1) * 32, EE, tid);
            ldg_w(sw, wh + (kc + 1) * 32, wl + (kc + 1) * 32, tid);
        }
        mma_chunk(ub[cur], lane, m_warp, n_warp, c);
        if (kc < 7) {
            sts_cvt(sa, buf[nxt] + BUF_AH, buf[nxt] + BUF_AL, tid);
            sts_w(sw, buf[nxt] + BUF_BH, buf[nxt] + BUF_BL, tid);
        }
        __syncthreads();
    }

    if (sel == 0) {
#pragma unroll
        for (int mi = 0; mi < 2; mi++)
#pragma unroll
            for (int nj = 0; nj < 8; nj++) {
                int r = m0 + m_warp + mi * 16 + (lane >> 2);
                int col = nh * 128 + n_warp + nj * 8 + (lane & 3) * 2;
                *(float2*)(g_qm + (size_t)r * EE + col) = make_float2(c[mi][nj][0], c[mi][nj][1]);
                *(float2*)(g_qm + (size_t)(r + 8) * EE + col) =
                    make_float2(c[mi][nj][2], c[mi][nj][3]);
            }
    } else {
#pragma unroll
        for (int mi = 0; mi < 2; mi++)
#pragma unroll
            for (int nj = 0; nj < 8; nj++) {
                int r = m0 + m_warp + mi * 16 + (lane >> 2);
                int col = nh * 128 + n_warp + nj * 8 + (lane & 3) * 2;
                int b0 = r >> 12, s0 = r & 4095;
                int b1 = (r + 8) >> 12, s1 = (r + 8) & 4095;
                g_uT[(size_t)b0 * EE * SS + (size_t)col * SS + s0] = c[mi][nj][0];
                g_uT[(size_t)b0 * EE * SS + (size_t)(col + 1) * SS + s0] = c[mi][nj][1];
                g_uT[(size_t)b1 * EE * SS + (size_t)col * SS + s1] = c[mi][nj][2];
                g_uT[(size_t)b1 * EE * SS + (size_t)(col + 1) * SS + s1] = c[mi][nj][3];
            }
    }
}

// ---------------- logits+exp: probs = exp(qm @ x^T) per (b,n,w).  grid (640,3) ----------------
__global__ __launch_bounds__(256) void logits_mma(const float* __restrict__ x) {
    const int tid = threadIdx.x, lane = tid & 31, wid = tid >> 5;
    const int bn = blockIdx.x;
    const int b = bn >> 5, n = bn & 31;
    const int w = blockIdx.y;
    const int j = n - 1 + w;
    float* Lbase = g_probs + (size_t)bn * (BLK * CTX) + w * 128;

    if (j < 0 || j >= NB) {
        // padded context block: exp(0) = 1 (only the rowsum consumes these)
#pragma unroll
        for (int t = 0; t < 16; t++) {
            int f4 = tid + 256 * t;
            int row = f4 >> 5, c4 = f4 & 31;
            *(float4*)(Lbase + (size_t)row * CTX + c4 * 4) = make_float4(1.f, 1.f, 1.f, 1.f);
        }
        return;
    }

    extern __shared__ __align__(16) char dsm[];
    const int m_warp = (wid >> 1) * 32, n_warp = (wid & 1) * 64;
    const float* qsrc = g_qm + (size_t)(b * SS + n * 128) * EE;
    const float* ksrc = x + (size_t)(b * SS + j * 128) * EE;
    char* buf[2] = {dsm, dsm + BUF_SZ};
    const uint32_t ub[2] = {smem_u32(buf[0]), smem_u32(buf[1])};

    float c[2][8][4];
#pragma unroll
    for (int i = 0; i < 2; i++)
#pragma unroll
        for (int jq = 0; jq < 8; jq++)
#pragma unroll
            for (int t = 0; t < 4; t++) c[i][jq][t] = 0.f;

    StageCvt sa, sb;
    ldg_cvt(sa, qsrc, EE, tid);
    ldg_cvt(sb, ksrc, EE, tid);
    sts_cvt(sa, buf[0] + BUF_AH, buf[0] + BUF_AL, tid);
    sts_cvt(sb, buf[0] + BUF_BH, buf[0] + BUF_BL, tid);
    __syncthreads();
    for (int kc = 0; kc < 8; kc++) {
        int cur = kc & 1, nxt = cur ^ 1;
        if (kc < 7) {
            ldg_cvt(sa, qsrc + (kc + 1) * 32, EE, tid);
            ldg_cvt(sb, ksrc + (kc + 1) * 32, EE, tid);
        }
        mma_chunk(ub[cur], lane, m_warp, n_warp, c);
        if (kc < 7) {
            sts_cvt(sa, buf[nxt] + BUF_AH, buf[nxt] + BUF_AL, tid);
            sts_cvt(sb, buf[nxt] + BUF_BH, buf[nxt] + BUF_BL, tid);
        }
        __syncthreads();
    }
#pragma unroll
    for (int mi = 0; mi < 2; mi++)
#pragma unroll
        for (int nj = 0; nj < 8; nj++) {
            int r = m_warp + mi * 16 + (lane >> 2);
            int col = n_warp + nj * 8 + (lane & 3) * 2;
            *(float2*)(Lbase + (size_t)r * CTX + col) =
                make_float2(__expf(c[mi][nj][0]), __expf(c[mi][nj][1]));
            *(float2*)(Lbase + (size_t)(r + 8) * CTX + col) =
                make_float2(__expf(c[mi][nj][2]), __expf(c[mi][nj][3]));
        }
}

// ---------------- rowsum: rinv = 1/sum(probs row).  one warp per row ----------------
__global__ __launch_bounds__(256) void rowsum_kernel() {
    const int gw = (blockIdx.x * blockDim.x + threadIdx.x) >> 5;
    const int lane = threadIdx.x & 31;
    const float* row = g_probs + (size_t)gw * CTX;
    float s = 0.f;
#pragma unroll
    for (int i = 0; i < 12; i++) s += row[lane + 32 * i];
#pragma unroll
    for (int o = 16; o > 0; o >>= 1) s += __shfl_xor_sync(0xFFFFFFFFu, s, o);
    if (lane == 0) g_rinv[gw] = 1.f / s;
}

// ---------------- AV+out: (probs @ uc) * rinv + bo -> d_out (permuted rows).  grid (640,2) ----------------
__global__ __launch_bounds__(256) void avo_mma(const float* __restrict__ bo,
                                               float* __restrict__ out) {
    extern __shared__ __align__(16) char dsm[];
    const int tid = threadIdx.x, lane = tid & 31, wid = tid >> 5;
    const int m_warp = (wid >> 1) * 32, n_warp = (wid & 1) * 64;
    const int bn = blockIdx.x;
    const int b = bn >> 5, n = bn & 31;
    const int n0 = blockIdx.y * 128;
    const float* psrc = g_probs + (size_t)bn * (BLK * CTX);
    const float* vsrc = g_uT + (size_t)b * EE * SS + (size_t)n0 * SS;
    char* buf[2] = {dsm, dsm + BUF_SZ};
    const uint32_t ub[2] = {smem_u32(buf[0]), smem_u32(buf[1])};

    // valid k-chunks (padded regions have u == 0 -> skip)
    int kcs[12], nk = 0;
#pragma unroll
    for (int kc = 0; kc < 12; kc++) {
        int key0 = (n - 1) * 128 + kc * 32;
        if (key0 >= 0 && key0 < SS) kcs[nk++] = kc;
    }

    float c[2][8][4];
#pragma unroll
    for (int i = 0; i < 2; i++)
#pragma unroll
        for (int jq = 0; jq < 8; jq++)
#pragma unroll
            for (int t = 0; t < 4; t++) c[i][jq][t] = 0.f;

    StageCvt sa, sb;
    ldg_cvt(sa, psrc + kcs[0] * 32, CTX, tid);
    ldg_cvt(sb, vsrc + (n - 1) * 128 + kcs[0] * 32, SS, tid);
    sts_cvt(sa, buf[0] + BUF_AH, buf[0] + BUF_AL, tid);
    sts_cvt(sb, buf[0] + BUF_BH, buf[0] + BUF_BL, tid);
    __syncthreads();
    for (int i = 0; i < nk; i++) {
        int cur = i & 1, nxt = cur ^ 1;
        if (i + 1 < nk) {
            ldg_cvt(sa, psrc + kcs[i + 1] * 32, CTX, tid);
            ldg_cvt(sb, vsrc + (n - 1) * 128 + kcs[i + 1] * 32, SS, tid);
        }
        mma_chunk(ub[cur], lane, m_warp, n_warp, c);
        if (i + 1 < nk) {
            sts_cvt(sa, buf[nxt] + BUF_AH, buf[nxt] + BUF_AL, tid);
            sts_cvt(sb, buf[nxt] + BUF_BH, buf[nxt] + BUF_BL, tid);
        }
        __syncthreads();
    }
    const int orow_base = n * (BB * 128) + b * 128;
#pragma unroll
    for (int mi = 0; mi < 2; mi++) {
        int rl = m_warp + mi * 16 + (lane >> 2);
        float ri0 = g_rinv[bn * 128 + rl];
        float ri1 = g_rinv[bn * 128 + rl + 8];
#pragma unroll
        for (int nj = 0; nj < 8; nj++) {
            int r = orow_base + rl;
            int col = n0 + n_warp + nj * 8 + (lane & 3) * 2;
            float2 bv = *(const float2*)(bo + col);
            *(float2*)(out + (size_t)r * EE + col) =
                make_float2(c[mi][nj][0] * ri0 + bv.x, c[mi][nj][1] * ri0 + bv.y);
            *(float2*)(out + (size_t)(r + 8) * EE + col) =
                make_float2(c[mi][nj][2] * ri1 + bv.x, c[mi][nj][3] * ri1 + bv.y);
        }
    }
}

// ---------------- launch ----------------
extern "C" void kernel_launch(void* const* d_in, const int* in_sizes, int n_in,
                              void* d_out, int out_size) {
    const float* x  = (const float*)d_in[0];
    const float* Wq = (const float*)d_in[1];
    const float* Wk = (const float*)d_in[2];
    const float* Wv = (const float*)d_in[3];
    const float* Wo = (const float*)d_in[4];
    const float* bo = (const float*)d_in[5];
    float* out = (float*)d_out;

    static bool attr_done = false;
    if (!attr_done) {
        cudaFuncSetAttribute(proj_mma, cudaFuncAttributeMaxDynamicSharedMemorySize, SMEM_PIPE);
        cudaFuncSetAttribute(logits_mma, cudaFuncAttributeMaxDynamicSharedMemorySize, SMEM_PIPE);
        cudaFuncSetAttribute(avo_mma, cudaFuncAttributeMaxDynamicSharedMemorySize, SMEM_PIPE);
        attr_done = true;
    }

    prep_mu<<<512, 256>>>(Wq, Wk, Wv, Wo);
    proj_mma<<<dim3(640, 4), 256, SMEM_PIPE>>>(x);
    logits_mma<<<dim3(640, 3), 256, SMEM_PIPE>>>(x);
    rowsum_kernel<<<10240, 256>>>();
    avo_mma<<<dim3(640, 2), 256, SMEM_PIPE>>>(bo, out);
}

// round 16
// speedup vs baseline: 1.6936x; 1.6936x over previous
#include <cuda_runtime.h>
#include <cuda_bf16.h>
#include <cstdint>

#define BB 20
#define SS 4096
#define EE 256
#define NB 32
#define BLK 128
#define CTX 384

// SMEM padded row stride in bytes (32 bf16 = 64B data + 16B pad, 16B-aligned rows)
#define SSTRIDE 80
// one buffer = Ah | Al | Bh | Bl, each 128*SSTRIDE = 10240 B
#define BUF_AH 0
#define BUF_AL 10240
#define BUF_BH 20480
#define BUF_BL 30720
#define BUF_SZ 40960
#define SMEM_PIPE (2 * BUF_SZ)  // 81920 B dynamic

// ---------------- device scratch ----------------
__device__ float g_qm[(size_t)BB * SS * EE];             // x @ (Wq Wk^T / 16)
__device__ float g_uT[(size_t)BB * EE * SS];             // (x @ Wv Wo) transposed [b][e][seq]
__device__ float g_probs[(size_t)BB * NB * BLK * CTX];   // exp(logits), unnormalized
__device__ float g_rinv[BB * NB * BLK];                  // 1/rowsum
__device__ __nv_bfloat16 g_mth[2][EE * EE];              // folded weights^T hi (0:M 1:U)
__device__ __nv_bfloat16 g_mtl[2][EE * EE];              // folded weights^T lo

// ---------------- PTX primitives ----------------
static __device__ __forceinline__ uint32_t smem_u32(const void* p) {
    return (uint32_t)__cvta_generic_to_shared(p);
}
static __device__ __forceinline__ void ldsm4(uint32_t& r0, uint32_t& r1, uint32_t& r2,
                                             uint32_t& r3, uint32_t addr) {
    asm volatile("ldmatrix.sync.aligned.m8n8.x4.shared.b16 {%0,%1,%2,%3}, [%4];"
                 : "=r"(r0), "=r"(r1), "=r"(r2), "=r"(r3) : "r"(addr));
}
static __device__ __forceinline__ void mma16816(float* c, const uint32_t* a, const uint32_t* b) {
    asm volatile(
        "mma.sync.aligned.m16n8k16.row.col.f32.bf16.bf16.f32 "
        "{%0,%1,%2,%3}, {%4,%5,%6,%7}, {%8,%9}, {%0,%1,%2,%3};"
        : "+f"(c[0]), "+f"(c[1]), "+f"(c[2]), "+f"(c[3])
        : "r"(a[0]), "r"(a[1]), "r"(a[2]), "r"(a[3]), "r"(b[0]), "r"(b[1]));
}

// ---------------- register staging: LDG early, convert+STS late ----------------
struct StageCvt { float4 v[4]; };
static __device__ __forceinline__ void ldg_cvt(StageCvt& st, const float* __restrict__ src,
                                               int lda, int tid) {
#pragma unroll
    for (int i = 0; i < 4; i++) {
        int f = tid + 256 * i;
        int row = f >> 3, c4 = f & 7;
        st.v[i] = *(const float4*)(src + (size_t)row * lda + c4 * 4);
    }
}
static __device__ __forceinline__ void sts_cvt(const StageCvt& st, char* shi, char* slo,
                                               int tid) {
#pragma unroll
    for (int i = 0; i < 4; i++) {
        int f = tid + 256 * i;
        int row = f >> 3, c4 = f & 7;
        float4 v = st.v[i];
        __nv_bfloat162 ha = __floats2bfloat162_rn(v.x, v.y);
        __nv_bfloat162 hb = __floats2bfloat162_rn(v.z, v.w);
        float2 fa = __bfloat1622float2(ha);
        float2 fb = __bfloat1622float2(hb);
        __nv_bfloat162 la = __floats2bfloat162_rn(v.x - fa.x, v.y - fa.y);
        __nv_bfloat162 lb = __floats2bfloat162_rn(v.z - fb.x, v.w - fb.y);
        int off = row * SSTRIDE + c4 * 8;
        *(uint2*)(shi + off) = make_uint2(*(uint32_t*)&ha, *(uint32_t*)&hb);
        *(uint2*)(slo + off) = make_uint2(*(uint32_t*)&la, *(uint32_t*)&lb);
    }
}
struct StageW { uint4 v[2][2]; };  // [i][0]=hi [i][1]=lo
static __device__ __forceinline__ void ldg_w(StageW& st, const __nv_bfloat16* __restrict__ wh,
                                             const __nv_bfloat16* __restrict__ wl, int tid) {
#pragma unroll
    for (int i = 0; i < 2; i++) {
        int f = tid + 256 * i;
        int row = f >> 2, c = f & 3;
        st.v[i][0] = *(const uint4*)(wh + (size_t)row * EE + c * 8);
        st.v[i][1] = *(const uint4*)(wl + (size_t)row * EE + c * 8);
    }
}
static __device__ __forceinline__ void sts_w(const StageW& st, char* shi, char* slo, int tid) {
#pragma unroll
    for (int i = 0; i < 2; i++) {
        int f = tid + 256 * i;
        int row = f >> 2, c = f & 3;
        int off = row * SSTRIDE + c * 16;
        *(uint4*)(shi + off) = st.v[i][0];
        *(uint4*)(slo + off) = st.v[i][1];
    }
}

// ---------------- one 32-k chunk of bf16x3 MMAs from buffer `base` ----------------
static __device__ __forceinline__ void mma_chunk(uint32_t base, int lane, int m_warp,
                                                 int n_warp, float c[2][8][4]) {
    const uint32_t uAh = base + BUF_AH, uAl = base + BUF_AL;
    const uint32_t uBh = base + BUF_BH, uBl = base + BUF_BL;
#pragma unroll
    for (int kk = 0; kk < 2; kk++) {
        const int kb = kk * 32;
        uint32_t ah[2][4], al[2][4], bh[8][2], bl[8][2];
        const uint32_t a_off =
            (uint32_t)((m_warp + (lane & 15)) * SSTRIDE + kb + ((lane >> 4) << 4));
        ldsm4(ah[0][0], ah[0][1], ah[0][2], ah[0][3], uAh + a_off);
        ldsm4(ah[1][0], ah[1][1], ah[1][2], ah[1][3], uAh + a_off + 16 * SSTRIDE);
        ldsm4(al[0][0], al[0][1], al[0][2], al[0][3], uAl + a_off);
        ldsm4(al[1][0], al[1][1], al[1][2], al[1][3], uAl + a_off + 16 * SSTRIDE);
        const int br = (lane & 7) + ((lane >> 4) << 3);
        const int bc = kb + (((lane >> 3) & 1) << 4);
#pragma unroll
        for (int j = 0; j < 4; j++) {
            const uint32_t b_off = (uint32_t)((n_warp + 16 * j + br) * SSTRIDE + bc);
            uint32_t r0, r1, r2, r3;
            ldsm4(r0, r1, r2, r3, uBh + b_off);
            bh[2 * j][0] = r0; bh[2 * j][1] = r1;
            bh[2 * j + 1][0] = r2; bh[2 * j + 1][1] = r3;
            ldsm4(r0, r1, r2, r3, uBl + b_off);
            bl[2 * j][0] = r0; bl[2 * j][1] = r1;
            bl[2 * j + 1][0] = r2; bl[2 * j + 1][1] = r3;
        }
#pragma unroll
        for (int mi = 0; mi < 2; mi++)
#pragma unroll
            for (int nj = 0; nj < 8; nj++) {
                mma16816(c[mi][nj], ah[mi], bh[nj]);
                mma16816(c[mi][nj], ah[mi], bl[nj]);
                mma16816(c[mi][nj], al[mi], bh[nj]);
            }
    }
}

// ---------------- folded-weight prep (smem-tiled fp32 GEMM, 8 CTAs) ----------------
// mat 0: M[k,n] = sum_e Wq[k,e]*Wk[n,e] / 16   (NT)
// mat 1: U[k,n] = sum_e Wv[k,e]*Wo[e,n]        (NN)
// store transposed hi/lo at g_mt*[mat][n*EE+k]
__global__ __launch_bounds__(256) void prep_mu_gemm(const float* __restrict__ Wq,
                                                    const float* __restrict__ Wk,
                                                    const float* __restrict__ Wv,
                                                    const float* __restrict__ Wo) {
    __shared__ float As[16][128];  // [e][k]
    __shared__ float Bs[16][128];  // [e][n]
    const int tid = threadIdx.x;
    const int tx = tid & 15, ty = tid >> 4;
    const int mat = blockIdx.x >> 2;
    const int k0 = ((blockIdx.x >> 1) & 1) * 128;
    const int n0 = (blockIdx.x & 1) * 128;
    const float* A = mat ? Wv : Wq;

    float acc[8][8];
#pragma unroll
    for (int i = 0; i < 8; i++)
#pragma unroll
        for (int j = 0; j < 8; j++) acc[i][j] = 0.f;

    for (int et = 0; et < EE; et += 16) {
        // A transposed load: 128 k-rows x 16 e-cols
#pragma unroll
        for (int t = 0; t < 2; t++) {
            int f4 = tid + 256 * t;
            int row = f4 >> 2, c4 = f4 & 3;
            float4 v = *(const float4*)(A + (size_t)(k0 + row) * EE + et + c4 * 4);
            As[c4 * 4 + 0][row] = v.x; As[c4 * 4 + 1][row] = v.y;
            As[c4 * 4 + 2][row] = v.z; As[c4 * 4 + 3][row] = v.w;
        }
        if (mat == 0) {
            // B = Wk^T: transposed load of Wk rows n
#pragma unroll
            for (int t = 0; t < 2; t++) {
                int f4 = tid + 256 * t;
                int row = f4 >> 2, c4 = f4 & 3;
                float4 v = *(const float4*)(Wk + (size_t)(n0 + row) * EE + et + c4 * 4);
                Bs[c4 * 4 + 0][row] = v.x; Bs[c4 * 4 + 1][row] = v.y;
                Bs[c4 * 4 + 2][row] = v.z; Bs[c4 * 4 + 3][row] = v.w;
            }
        } else {
            // B = Wo natural load: 16 e-rows x 128 n-cols
#pragma unroll
            for (int t = 0; t < 2; t++) {
                int f4 = tid + 256 * t;
                int row = f4 >> 5, c4 = f4 & 31;
                float4 v = *(const float4*)(Wo + (size_t)(et + row) * EE + n0 + c4 * 4);
                *(float4*)&Bs[row][c4 * 4] = v;
            }
        }
        __syncthreads();
#pragma unroll
        for (int kk = 0; kk < 16; kk++) {
            float4 a0 = *(float4*)&As[kk][ty * 4];
            float4 a1 = *(float4*)&As[kk][ty * 4 + 64];
            float4 b0 = *(float4*)&Bs[kk][tx * 4];
            float4 b1 = *(float4*)&Bs[kk][tx * 4 + 64];
            float a[8] = {a0.x, a0.y, a0.z, a0.w, a1.x, a1.y, a1.z, a1.w};
            float b[8] = {b0.x, b0.y, b0.z, b0.w, b1.x, b1.y, b1.z, b1.w};
#pragma unroll
            for (int i = 0; i < 8; i++)
#pragma unroll
                for (int j = 0; j < 8; j++) acc[i][j] += a[i] * b[j];
        }
        __syncthreads();
    }
    const float scale = mat ? 1.0f : 0.0625f;
#pragma unroll
    for (int ii = 0; ii < 2; ii++)
#pragma unroll
        for (int i = 0; i < 4; i++) {
            int k = k0 + ty * 4 + 64 * ii + i;
#pragma unroll
            for (int jj = 0; jj < 2; jj++)
#pragma unroll
                for (int j = 0; j < 4; j++) {
                    int n = n0 + tx * 4 + 64 * jj + j;
                    float s = acc[ii * 4 + i][jj * 4 + j] * scale;
                    __nv_bfloat16 h = __float2bfloat16_rn(s);
                    g_mth[mat][n * EE + k] = h;
                    g_mtl[mat][n * EE + k] = __float2bfloat16_rn(s - __bfloat162float(h));
                }
        }
}

// ---------------- projections: qm = x@M, u = x@U (u stored transposed). grid (640,4) ----------------
__global__ __launch_bounds__(256) void proj_mma(const float* __restrict__ x) {
    extern __shared__ __align__(16) char dsm[];
    const int tid = threadIdx.x, lane = tid & 31, wid = tid >> 5;
    const int m_warp = (wid >> 1) * 32, n_warp = (wid & 1) * 64;
    const int m0 = blockIdx.x * 128;
    const int sel = blockIdx.y >> 1, nh = blockIdx.y & 1;
    const __nv_bfloat16* wh = g_mth[sel] + (size_t)nh * 128 * EE;
    const __nv_bfloat16* wl = g_mtl[sel] + (size_t)nh * 128 * EE;
    const float* asrc = x + (size_t)m0 * EE;
    char* buf[2] = {dsm, dsm + BUF_SZ};
    const uint32_t ub[2] = {smem_u32(buf[0]), smem_u32(buf[1])};

    float c[2][8][4];
#pragma unroll
    for (int i = 0; i < 2; i++)
#pragma unroll
        for (int j = 0; j < 8; j++)
#pragma unroll
            for (int t = 0; t < 4; t++) c[i][j][t] = 0.f;

    StageCvt sa; StageW sw;
    ldg_cvt(sa, asrc, EE, tid);
    ldg_w(sw, wh, wl, tid);
    sts_cvt(sa, buf[0] + BUF_AH, buf[0] + BUF_AL, tid);
    sts_w(sw, buf[0] + BUF_BH, buf[0] + BUF_BL, tid);
    __syncthreads();
    for (int kc = 0; kc < 8; kc++) {
        int cur = kc & 1, nxt = cur ^ 1;
        if (kc < 7) {
            ldg_cvt(sa, asrc + (kc + 1) * 32, EE, tid);
            ldg_w(sw, wh + (kc + 1) * 32, wl + (kc + 1) * 32, tid);
        }
        mma_chunk(ub[cur], lane, m_warp, n_warp, c);
        if (kc < 7) {
            sts_cvt(sa, buf[nxt] + BUF_AH, buf[nxt] + BUF_AL, tid);
            sts_w(sw, buf[nxt] + BUF_BH, buf[nxt] + BUF_BL, tid);
        }
        __syncthreads();
    }

    if (sel == 0) {
#pragma unroll
        for (int mi = 0; mi < 2; mi++)
#pragma unroll
            for (int nj = 0; nj < 8; nj++) {
                int r = m0 + m_warp + mi * 16 + (lane >> 2);
                int col = nh * 128 + n_warp + nj * 8 + (lane & 3) * 2;
                *(float2*)(g_qm + (size_t)r * EE + col) = make_float2(c[mi][nj][0], c[mi][nj][1]);
                *(float2*)(g_qm + (size_t)(r + 8) * EE + col) =
                    make_float2(c[mi][nj][2], c[mi][nj][3]);
            }
    } else {
#pragma unroll
        for (int mi = 0; mi < 2; mi++)
#pragma unroll
            for (int nj = 0; nj < 8; nj++) {
                int r = m0 + m_warp + mi * 16 + (lane >> 2);
                int col = nh * 128 + n_warp + nj * 8 + (lane & 3) * 2;
                int b0 = r >> 12, s0 = r & 4095;
                int b1 = (r + 8) >> 12, s1 = (r + 8) & 4095;
                g_uT[(size_t)b0 * EE * SS + (size_t)col * SS + s0] = c[mi][nj][0];
                g_uT[(size_t)b0 * EE * SS + (size_t)(col + 1) * SS + s0] = c[mi][nj][1];
                g_uT[(size_t)b1 * EE * SS + (size_t)col * SS + s1] = c[mi][nj][2];
                g_uT[(size_t)b1 * EE * SS + (size_t)(col + 1) * SS + s1] = c[mi][nj][3];
            }
    }
}

// ---------------- logits+exp: probs = exp(qm @ x^T) per (b,n,w).  grid (640,3) ----------------
__global__ __launch_bounds__(256) void logits_mma(const float* __restrict__ x) {
    const int tid = threadIdx.x, lane = tid & 31, wid = tid >> 5;
    const int bn = blockIdx.x;
    const int b = bn >> 5, n = bn & 31;
    const int w = blockIdx.y;
    const int j = n - 1 + w;
    float* Lbase = g_probs + (size_t)bn * (BLK * CTX) + w * 128;

    if (j < 0 || j >= NB) {
        // padded context block: exp(0) = 1 (only the rowsum consumes these)
#pragma unroll
        for (int t = 0; t < 16; t++) {
            int f4 = tid + 256 * t;
            int row = f4 >> 5, c4 = f4 & 31;
            *(float4*)(Lbase + (size_t)row * CTX + c4 * 4) = make_float4(1.f, 1.f, 1.f, 1.f);
        }
        return;
    }

    extern __shared__ __align__(16) char dsm[];
    const int m_warp = (wid >> 1) * 32, n_warp = (wid & 1) * 64;
    const float* qsrc = g_qm + (size_t)(b * SS + n * 128) * EE;
    const float* ksrc = x + (size_t)(b * SS + j * 128) * EE;
    char* buf[2] = {dsm, dsm + BUF_SZ};
    const uint32_t ub[2] = {smem_u32(buf[0]), smem_u32(buf[1])};

    float c[2][8][4];
#pragma unroll
    for (int i = 0; i < 2; i++)
#pragma unroll
        for (int jq = 0; jq < 8; jq++)
#pragma unroll
            for (int t = 0; t < 4; t++) c[i][jq][t] = 0.f;

    StageCvt sa, sb;
    ldg_cvt(sa, qsrc, EE, tid);
    ldg_cvt(sb, ksrc, EE, tid);
    sts_cvt(sa, buf[0] + BUF_AH, buf[0] + BUF_AL, tid);
    sts_cvt(sb, buf[0] + BUF_BH, buf[0] + BUF_BL, tid);
    __syncthreads();
    for (int kc = 0; kc < 8; kc++) {
        int cur = kc & 1, nxt = cur ^ 1;
        if (kc < 7) {
            ldg_cvt(sa, qsrc + (kc + 1) * 32, EE, tid);
            ldg_cvt(sb, ksrc + (kc + 1) * 32, EE, tid);
        }
        mma_chunk(ub[cur], lane, m_warp, n_warp, c);
        if (kc < 7) {
            sts_cvt(sa, buf[nxt] + BUF_AH, buf[nxt] + BUF_AL, tid);
            sts_cvt(sb, buf[nxt] + BUF_BH, buf[nxt] + BUF_BL, tid);
        }
        __syncthreads();
    }
#pragma unroll
    for (int mi = 0; mi < 2; mi++)
#pragma unroll
        for (int nj = 0; nj < 8; nj++) {
            int r = m_warp + mi * 16 + (lane >> 2);
            int col = n_warp + nj * 8 + (lane & 3) * 2;
            *(float2*)(Lbase + (size_t)r * CTX + col) =
                make_float2(__expf(c[mi][nj][0]), __expf(c[mi][nj][1]));
            *(float2*)(Lbase + (size_t)(r + 8) * CTX + col) =
                make_float2(__expf(c[mi][nj][2]), __expf(c[mi][nj][3]));
        }
}

// ---------------- rowsum: rinv = 1/sum(probs row).  one warp per row ----------------
__global__ __launch_bounds__(256) void rowsum_kernel() {
    const int gw = (blockIdx.x * blockDim.x + threadIdx.x) >> 5;
    const int lane = threadIdx.x & 31;
    const float* row = g_probs + (size_t)gw * CTX;
    float s = 0.f;
#pragma unroll
    for (int i = 0; i < 12; i++) s += row[lane + 32 * i];
#pragma unroll
    for (int o = 16; o > 0; o >>= 1) s += __shfl_xor_sync(0xFFFFFFFFu, s, o);
    if (lane == 0) g_rinv[gw] = 1.f / s;
}

// ---------------- AV+out: (probs @ uc) * rinv + bo -> d_out (permuted rows).  grid (640,2) ----------------
__global__ __launch_bounds__(256) void avo_mma(const float* __restrict__ bo,
                                               float* __restrict__ out) {
    extern __shared__ __align__(16) char dsm[];
    const int tid = threadIdx.x, lane = tid & 31, wid = tid >> 5;
    const int m_warp = (wid >> 1) * 32, n_warp = (wid & 1) * 64;
    const int bn = blockIdx.x;
    const int b = bn >> 5, n = bn & 31;
    const int n0 = blockIdx.y * 128;
    const float* psrc = g_probs + (size_t)bn * (BLK * CTX);
    const float* vsrc = g_uT + (size_t)b * EE * SS + (size_t)n0 * SS;
    char* buf[2] = {dsm, dsm + BUF_SZ};
    const uint32_t ub[2] = {smem_u32(buf[0]), smem_u32(buf[1])};

    // valid k-chunks (padded regions have u == 0 -> skip)
    int kcs[12], nk = 0;
#pragma unroll
    for (int kc = 0; kc < 12; kc++) {
        int key0 = (n - 1) * 128 + kc * 32;
        if (key0 >= 0 && key0 < SS) kcs[nk++] = kc;
    }

    float c[2][8][4];
#pragma unroll
    for (int i = 0; i < 2; i++)
#pragma unroll
        for (int jq = 0; jq < 8; jq++)
#pragma unroll
            for (int t = 0; t < 4; t++) c[i][jq][t] = 0.f;

    StageCvt sa, sb;
    ldg_cvt(sa, psrc + kcs[0] * 32, CTX, tid);
    ldg_cvt(sb, vsrc + (n - 1) * 128 + kcs[0] * 32, SS, tid);
    sts_cvt(sa, buf[0] + BUF_AH, buf[0] + BUF_AL, tid);
    sts_cvt(sb, buf[0] + BUF_BH, buf[0] + BUF_BL, tid);
    __syncthreads();
    for (int i = 0; i < nk; i++) {
        int cur = i & 1, nxt = cur ^ 1;
        if (i + 1 < nk) {
            ldg_cvt(sa, psrc + kcs[i + 1] * 32, CTX, tid);
            ldg_cvt(sb, vsrc + (n - 1) * 128 + kcs[i + 1] * 32, SS, tid);
        }
        mma_chunk(ub[cur], lane, m_warp, n_warp, c);
        if (i + 1 < nk) {
            sts_cvt(sa, buf[nxt] + BUF_AH, buf[nxt] + BUF_AL, tid);
            sts_cvt(sb, buf[nxt] + BUF_BH, buf[nxt] + BUF_BL, tid);
        }
        __syncthreads();
    }
    const int orow_base = n * (BB * 128) + b * 128;
#pragma unroll
    for (int mi = 0; mi < 2; mi++) {
        int rl = m_warp + mi * 16 + (lane >> 2);
        float ri0 = g_rinv[bn * 128 + rl];
        float ri1 = g_rinv[bn * 128 + rl + 8];
#pragma unroll
        for (int nj = 0; nj < 8; nj++) {
            int r = orow_base + rl;
            int col = n0 + n_warp + nj * 8 + (lane & 3) * 2;
            float2 bv = *(const float2*)(bo + col);
            *(float2*)(out + (size_t)r * EE + col) =
                make_float2(c[mi][nj][0] * ri0 + bv.x, c[mi][nj][1] * ri0 + bv.y);
            *(float2*)(out + (size_t)(r + 8) * EE + col) =
                make_float2(c[mi][nj][2] * ri1 + bv.x, c[mi][nj][3] * ri1 + bv.y);
        }
    }
}

// ---------------- launch ----------------
extern "C" void kernel_launch(void* const* d_in, const int* in_sizes, int n_in,
                              void* d_out, int out_size) {
    const float* x  = (const float*)d_in[0];
    const float* Wq = (const float*)d_in[1];
    const float* Wk = (const float*)d_in[2];
    const float* Wv = (const float*)d_in[3];
    const float* Wo = (const float*)d_in[4];
    const float* bo = (const float*)d_in[5];
    float* out = (float*)d_out;

    static bool attr_done = false;
    if (!attr_done) {
        cudaFuncSetAttribute(proj_mma, cudaFuncAttributeMaxDynamicSharedMemorySize, SMEM_PIPE);
        cudaFuncSetAttribute(logits_mma, cudaFuncAttributeMaxDynamicSharedMemorySize, SMEM_PIPE);
        cudaFuncSetAttribute(avo_mma, cudaFuncAttributeMaxDynamicSharedMemorySize, SMEM_PIPE);
        attr_done = true;
    }

    prep_mu_gemm<<<8, 256>>>(Wq, Wk, Wv, Wo);
    proj_mma<<<dim3(640, 4), 256, SMEM_PIPE>>>(x);
    logits_mma<<<dim3(640, 3), 256, SMEM_PIPE>>>(x);
    rowsum_kernel<<<10240, 256>>>();
    avo_mma<<<dim3(640, 2), 256, SMEM_PIPE>>>(bo, out);
}

// round 17
// speedup vs baseline: 1.7296x; 1.0213x over previous
#include <cuda_runtime.h>
#include <cuda_bf16.h>
#include <cstdint>

#define BB 20
#define SS 4096
#define EE 256
#define NB 32
#define BLK 128
#define CTX 384

// ---- avo (per-chunk joint A+B) buffers, as R16 ----
#define SSTRIDE 80
#define BUF_AH 0
#define BUF_AL 10240
#define BUF_BH 20480
#define BUF_BL 30720
#define BUF_SZ 40960
#define SMEM_PIPE (2 * BUF_SZ)  // 81920

// ---- full-K A-resident layout (proj_full / logits_full) ----
#define ASTRIDE 528                       // 256 bf16 = 512B + 16B pad (33*16 -> ldsm conflict-free)
#define A_HI 0
#define A_LO (128 * ASTRIDE)              // 67584
#define B_PIPE (2 * 128 * ASTRIDE)        // 135168: B double-buffer region
#define BBUF_SZ 20480                     // Bh(10240) + Bl(10240)
#define SMEM_FULL (B_PIPE + 2 * BBUF_SZ)  // 176128

// ---------------- device scratch ----------------
__device__ float g_qm[(size_t)BB * SS * EE];             // x @ (Wq Wk^T / 16)
__device__ float g_uT[(size_t)BB * EE * SS];             // (x @ Wv Wo) transposed [b][e][seq]
__device__ float g_probs[(size_t)BB * NB * BLK * CTX];   // exp(logits), unnormalized
__device__ float g_rinv[BB * NB * BLK];                  // 1/rowsum
__device__ __nv_bfloat16 g_mth[2][EE * EE];              // folded weights^T hi (0:M 1:U)
__device__ __nv_bfloat16 g_mtl[2][EE * EE];              // folded weights^T lo

// ---------------- PTX primitives ----------------
static __device__ __forceinline__ uint32_t smem_u32(const void* p) {
    return (uint32_t)__cvta_generic_to_shared(p);
}
static __device__ __forceinline__ void ldsm4(uint32_t& r0, uint32_t& r1, uint32_t& r2,
                                             uint32_t& r3, uint32_t addr) {
    asm volatile("ldmatrix.sync.aligned.m8n8.x4.shared.b16 {%0,%1,%2,%3}, [%4];"
                 : "=r"(r0), "=r"(r1), "=r"(r2), "=r"(r3) : "r"(addr));
}
static __device__ __forceinline__ void mma16816(float* c, const uint32_t* a, const uint32_t* b) {
    asm volatile(
        "mma.sync.aligned.m16n8k16.row.col.f32.bf16.bf16.f32 "
        "{%0,%1,%2,%3}, {%4,%5,%6,%7}, {%8,%9}, {%0,%1,%2,%3};"
        : "+f"(c[0]), "+f"(c[1]), "+f"(c[2]), "+f"(c[3])
        : "r"(a[0]), "r"(a[1]), "r"(a[2]), "r"(a[3]), "r"(b[0]), "r"(b[1]));
}
static __device__ __forceinline__ void cvt_hi_lo(float4 v, uint2& h, uint2& l) {
    __nv_bfloat162 ha = __floats2bfloat162_rn(v.x, v.y);
    __nv_bfloat162 hb = __floats2bfloat162_rn(v.z, v.w);
    float2 fa = __bfloat1622float2(ha);
    float2 fb = __bfloat1622float2(hb);
    __nv_bfloat162 la = __floats2bfloat162_rn(v.x - fa.x, v.y - fa.y);
    __nv_bfloat162 lb = __floats2bfloat162_rn(v.z - fb.x, v.w - fb.y);
    h = make_uint2(*(uint32_t*)&ha, *(uint32_t*)&hb);
    l = make_uint2(*(uint32_t*)&la, *(uint32_t*)&lb);
}

// ---------------- staging (per-chunk 128x32), used by B pipes and avo ----------------
struct StageCvt { float4 v[4]; };
static __device__ __forceinline__ void ldg_cvt(StageCvt& st, const float* __restrict__ src,
                                               int lda, int tid) {
#pragma unroll
    for (int i = 0; i < 4; i++) {
        int f = tid + 256 * i;
        int row = f >> 3, c4 = f & 7;
        st.v[i] = *(const float4*)(src + (size_t)row * lda + c4 * 4);
    }
}
static __device__ __forceinline__ void sts_cvt(const StageCvt& st, char* shi, char* slo,
                                               int tid) {
#pragma unroll
    for (int i = 0; i < 4; i++) {
        int f = tid + 256 * i;
        int row = f >> 3, c4 = f & 7;
        uint2 h, l;
        cvt_hi_lo(st.v[i], h, l);
        int off = row * SSTRIDE + c4 * 8;
        *(uint2*)(shi + off) = h;
        *(uint2*)(slo + off) = l;
    }
}
struct StageW { uint4 v[2][2]; };
static __device__ __forceinline__ void ldg_w(StageW& st, const __nv_bfloat16* __restrict__ wh,
                                             const __nv_bfloat16* __restrict__ wl, int tid) {
#pragma unroll
    for (int i = 0; i < 2; i++) {
        int f = tid + 256 * i;
        int row = f >> 2, c = f & 3;
        st.v[i][0] = *(const uint4*)(wh + (size_t)row * EE + c * 8);
        st.v[i][1] = *(const uint4*)(wl + (size_t)row * EE + c * 8);
    }
}
static __device__ __forceinline__ void sts_w(const StageW& st, char* shi, char* slo, int tid) {
#pragma unroll
    for (int i = 0; i < 2; i++) {
        int f = tid + 256 * i;
        int row = f >> 2, c = f & 3;
        int off = row * SSTRIDE + c * 16;
        *(uint4*)(shi + off) = st.v[i][0];
        *(uint4*)(slo + off) = st.v[i][1];
    }
}

// ---------------- full-K A fill: 128 rows x 256 cols fp32 -> hi/lo bf16 ----------------
static __device__ __forceinline__ void fill_A(const float* __restrict__ src, char* smA,
                                              int tid) {
#pragma unroll
    for (int i = 0; i < 32; i++) {
        int f = tid + 256 * i;
        int row = f >> 6, c4 = f & 63;
        float4 v = *(const float4*)(src + (size_t)row * EE + c4 * 4);
        uint2 h, l;
        cvt_hi_lo(v, h, l);
        int off = row * ASTRIDE + c4 * 8;
        *(uint2*)(smA + A_HI + off) = h;
        *(uint2*)(smA + A_LO + off) = l;
    }
}

// ---------------- MMA chunk, A from full-K resident region ----------------
static __device__ __forceinline__ void mma_chunkA(uint32_t uA, int aoff, uint32_t bb, int lane,
                                                  int m_warp, int n_warp, float c[2][8][4]) {
    const uint32_t uAh = uA + A_HI, uAl = uA + A_LO;
    const uint32_t uBh = bb, uBl = bb + 10240;
#pragma unroll
    for (int kk = 0; kk < 2; kk++) {
        const int kb = kk * 32;
        uint32_t ah[2][4], al[2][4], bh[8][2], bl[8][2];
        const uint32_t a_off =
            (uint32_t)((m_warp + (lane & 15)) * ASTRIDE + aoff + kb + ((lane >> 4) << 4));
        ldsm4(ah[0][0], ah[0][1], ah[0][2], ah[0][3], uAh + a_off);
        ldsm4(ah[1][0], ah[1][1], ah[1][2], ah[1][3], uAh + a_off + 16 * ASTRIDE);
        ldsm4(al[0][0], al[0][1], al[0][2], al[0][3], uAl + a_off);
        ldsm4(al[1][0], al[1][1], al[1][2], al[1][3], uAl + a_off + 16 * ASTRIDE);
        const int br = (lane & 7) + ((lane >> 4) << 3);
        const int bc = kb + (((lane >> 3) & 1) << 4);
#pragma unroll
        for (int j = 0; j < 4; j++) {
            const uint32_t b_off = (uint32_t)((n_warp + 16 * j + br) * SSTRIDE + bc);
            uint32_t r0, r1, r2, r3;
            ldsm4(r0, r1, r2, r3, uBh + b_off);
            bh[2 * j][0] = r0; bh[2 * j][1] = r1;
            bh[2 * j + 1][0] = r2; bh[2 * j + 1][1] = r3;
            ldsm4(r0, r1, r2, r3, uBl + b_off);
            bl[2 * j][0] = r0; bl[2 * j][1] = r1;
            bl[2 * j + 1][0] = r2; bl[2 * j + 1][1] = r3;
        }
#pragma unroll
        for (int mi = 0; mi < 2; mi++)
#pragma unroll
            for (int nj = 0; nj < 8; nj++) {
                mma16816(c[mi][nj], ah[mi], bh[nj]);
                mma16816(c[mi][nj], ah[mi], bl[nj]);
                mma16816(c[mi][nj], al[mi], bh[nj]);
            }
    }
}

// ---------------- MMA chunk, A+B both per-chunk (avo) ----------------
static __device__ __forceinline__ void mma_chunk(uint32_t base, int lane, int m_warp,
                                                 int n_warp, float c[2][8][4]) {
    const uint32_t uAh = base + BUF_AH, uAl = base + BUF_AL;
    const uint32_t uBh = base + BUF_BH, uBl = base + BUF_BL;
#pragma unroll
    for (int kk = 0; kk < 2; kk++) {
        const int kb = kk * 32;
        uint32_t ah[2][4], al[2][4], bh[8][2], bl[8][2];
        const uint32_t a_off =
            (uint32_t)((m_warp + (lane & 15)) * SSTRIDE + kb + ((lane >> 4) << 4));
        ldsm4(ah[0][0], ah[0][1], ah[0][2], ah[0][3], uAh + a_off);
        ldsm4(ah[1][0], ah[1][1], ah[1][2], ah[1][3], uAh + a_off + 16 * SSTRIDE);
        ldsm4(al[0][0], al[0][1], al[0][2], al[0][3], uAl + a_off);
        ldsm4(al[1][0], al[1][1], al[1][2], al[1][3], uAl + a_off + 16 * SSTRIDE);
        const int br = (lane & 7) + ((lane >> 4) << 3);
        const int bc = kb + (((lane >> 3) & 1) << 4);
#pragma unroll
        for (int j = 0; j < 4; j++) {
            const uint32_t b_off = (uint32_t)((n_warp + 16 * j + br) * SSTRIDE + bc);
            uint32_t r0, r1, r2, r3;
            ldsm4(r0, r1, r2, r3, uBh + b_off);
            bh[2 * j][0] = r0; bh[2 * j][1] = r1;
            bh[2 * j + 1][0] = r2; bh[2 * j + 1][1] = r3;
            ldsm4(r0, r1, r2, r3, uBl + b_off);
            bl[2 * j][0] = r0; bl[2 * j][1] = r1;
            bl[2 * j + 1][0] = r2; bl[2 * j + 1][1] = r3;
        }
#pragma unroll
        for (int mi = 0; mi < 2; mi++)
#pragma unroll
            for (int nj = 0; nj < 8; nj++) {
                mma16816(c[mi][nj], ah[mi], bh[nj]);
                mma16816(c[mi][nj], ah[mi], bl[nj]);
                mma16816(c[mi][nj], al[mi], bh[nj]);
            }
    }
}

// ---------------- folded-weight prep (smem-tiled fp32 GEMM, 8 CTAs) ----------------
__global__ __launch_bounds__(256) void prep_mu_gemm(const float* __restrict__ Wq,
                                                    const float* __restrict__ Wk,
                                                    const float* __restrict__ Wv,
                                                    const float* __restrict__ Wo) {
    __shared__ float As[16][128];
    __shared__ float Bs[16][128];
    const int tid = threadIdx.x;
    const int tx = tid & 15, ty = tid >> 4;
    const int mat = blockIdx.x >> 2;
    const int k0 = ((blockIdx.x >> 1) & 1) * 128;
    const int n0 = (blockIdx.x & 1) * 128;
    const float* A = mat ? Wv : Wq;

    float acc[8][8];
#pragma unroll
    for (int i = 0; i < 8; i++)
#pragma unroll
        for (int j = 0; j < 8; j++) acc[i][j] = 0.f;

    for (int et = 0; et < EE; et += 16) {
#pragma unroll
        for (int t = 0; t < 2; t++) {
            int f4 = tid + 256 * t;
            int row = f4 >> 2, c4 = f4 & 3;
            float4 v = *(const float4*)(A + (size_t)(k0 + row) * EE + et + c4 * 4);
            As[c4 * 4 + 0][row] = v.x; As[c4 * 4 + 1][row] = v.y;
            As[c4 * 4 + 2][row] = v.z; As[c4 * 4 + 3][row] = v.w;
        }
        if (mat == 0) {
#pragma unroll
            for (int t = 0; t < 2; t++) {
                int f4 = tid + 256 * t;
                int row = f4 >> 2, c4 = f4 & 3;
                float4 v = *(const float4*)(Wk + (size_t)(n0 + row) * EE + et + c4 * 4);
                Bs[c4 * 4 + 0][row] = v.x; Bs[c4 * 4 + 1][row] = v.y;
                Bs[c4 * 4 + 2][row] = v.z; Bs[c4 * 4 + 3][row] = v.w;
            }
        } else {
#pragma unroll
            for (int t = 0; t < 2; t++) {
                int f4 = tid + 256 * t;
                int row = f4 >> 5, c4 = f4 & 31;
                float4 v = *(const float4*)(Wo + (size_t)(et + row) * EE + n0 + c4 * 4);
                *(float4*)&Bs[row][c4 * 4] = v;
            }
        }
        __syncthreads();
#pragma unroll
        for (int kk = 0; kk < 16; kk++) {
            float4 a0 = *(float4*)&As[kk][ty * 4];
            float4 a1 = *(float4*)&As[kk][ty * 4 + 64];
            float4 b0 = *(float4*)&Bs[kk][tx * 4];
            float4 b1 = *(float4*)&Bs[kk][tx * 4 + 64];
            float a[8] = {a0.x, a0.y, a0.z, a0.w, a1.x, a1.y, a1.z, a1.w};
            float b[8] = {b0.x, b0.y, b0.z, b0.w, b1.x, b1.y, b1.z, b1.w};
#pragma unroll
            for (int i = 0; i < 8; i++)
#pragma unroll
                for (int j = 0; j < 8; j++) acc[i][j] += a[i] * b[j];
        }
        __syncthreads();
    }
    const float scale = mat ? 1.0f : 0.0625f;
#pragma unroll
    for (int ii = 0; ii < 2; ii++)
#pragma unroll
        for (int i = 0; i < 4; i++) {
            int k = k0 + ty * 4 + 64 * ii + i;
#pragma unroll
            for (int jj = 0; jj < 2; jj++)
#pragma unroll
                for (int j = 0; j < 4; j++) {
                    int n = n0 + tx * 4 + 64 * jj + j;
                    float s = acc[ii * 4 + i][jj * 4 + j] * scale;
                    __nv_bfloat16 h = __float2bfloat16_rn(s);
                    g_mth[mat][n * EE + k] = h;
                    g_mtl[mat][n * EE + k] = __float2bfloat16_rn(s - __bfloat162float(h));
                }
        }
}

// ---------------- proj_full: A=x tile resident; loop 4 outputs (qm/uT x col-half). grid 640 ----------------
__global__ __launch_bounds__(256) void proj_full(const float* __restrict__ x) {
    extern __shared__ __align__(16) char dsm[];
    const int tid = threadIdx.x, lane = tid & 31, wid = tid >> 5;
    const int m_warp = (wid >> 1) * 32, n_warp = (wid & 1) * 64;
    const int m0 = blockIdx.x * 128;
    const uint32_t uA = smem_u32(dsm);
    char* bbuf[2] = {dsm + B_PIPE, dsm + B_PIPE + BBUF_SZ};
    const uint32_t ub[2] = {smem_u32(bbuf[0]), smem_u32(bbuf[1])};

    fill_A(x + (size_t)m0 * EE, dsm, tid);
    __syncthreads();

    for (int o = 0; o < 4; o++) {
        const int sel = o >> 1, nh = o & 1;
        const __nv_bfloat16* wh = g_mth[sel] + (size_t)nh * 128 * EE;
        const __nv_bfloat16* wl = g_mtl[sel] + (size_t)nh * 128 * EE;

        float c[2][8][4];
#pragma unroll
        for (int i = 0; i < 2; i++)
#pragma unroll
            for (int j = 0; j < 8; j++)
#pragma unroll
                for (int t = 0; t < 4; t++) c[i][j][t] = 0.f;

        StageW sw;
        ldg_w(sw, wh, wl, tid);
        sts_w(sw, bbuf[0], bbuf[0] + 10240, tid);
        __syncthreads();
        for (int kc = 0; kc < 8; kc++) {
            int cur = kc & 1, nxt = cur ^ 1;
            if (kc < 7) ldg_w(sw, wh + (kc + 1) * 32, wl + (kc + 1) * 32, tid);
            mma_chunkA(uA, kc * 64, ub[cur], lane, m_warp, n_warp, c);
            if (kc < 7) sts_w(sw, bbuf[nxt], bbuf[nxt] + 10240, tid);
            __syncthreads();
        }

        if (sel == 0) {
#pragma unroll
            for (int mi = 0; mi < 2; mi++)
#pragma unroll
                for (int nj = 0; nj < 8; nj++) {
                    int r = m0 + m_warp + mi * 16 + (lane >> 2);
                    int col = nh * 128 + n_warp + nj * 8 + (lane & 3) * 2;
                    *(float2*)(g_qm + (size_t)r * EE + col) =
                        make_float2(c[mi][nj][0], c[mi][nj][1]);
                    *(float2*)(g_qm + (size_t)(r + 8) * EE + col) =
                        make_float2(c[mi][nj][2], c[mi][nj][3]);
                }
        } else {
#pragma unroll
            for (int mi = 0; mi < 2; mi++)
#pragma unroll
                for (int nj = 0; nj < 8; nj++) {
                    int r = m0 + m_warp + mi * 16 + (lane >> 2);
                    int col = nh * 128 + n_warp + nj * 8 + (lane & 3) * 2;
                    int b0 = r >> 12, s0 = r & 4095;
                    int b1 = (r + 8) >> 12, s1 = (r + 8) & 4095;
                    g_uT[(size_t)b0 * EE * SS + (size_t)col * SS + s0] = c[mi][nj][0];
                    g_uT[(size_t)b0 * EE * SS + (size_t)(col + 1) * SS + s0] = c[mi][nj][1];
                    g_uT[(size_t)b1 * EE * SS + (size_t)col * SS + s1] = c[mi][nj][2];
                    g_uT[(size_t)b1 * EE * SS + (size_t)(col + 1) * SS + s1] = c[mi][nj][3];
                }
        }
        __syncthreads();
    }
}

// ---------------- logits_full: A=qm resident; loop 3 windows; exp + rowsum + rinv. grid 640 ----------------
__global__ __launch_bounds__(256) void logits_full(const float* __restrict__ x) {
    extern __shared__ __align__(16) char dsm[];
    const int tid = threadIdx.x, lane = tid & 31, wid = tid >> 5;
    const int m_warp = (wid >> 1) * 32, n_warp = (wid & 1) * 64;
    const int bn = blockIdx.x;
    const int b = bn >> 5, n = bn & 31;
    const uint32_t uA = smem_u32(dsm);
    char* bbuf[2] = {dsm + B_PIPE, dsm + B_PIPE + BBUF_SZ};
    const uint32_t ub[2] = {smem_u32(bbuf[0]), smem_u32(bbuf[1])};

    fill_A(g_qm + (size_t)(b * SS + n * 128) * EE, dsm, tid);
    __syncthreads();

    float sacc[4] = {0.f, 0.f, 0.f, 0.f};  // row partial sums: rows m_warp + {g, g+8, g+16, g+24}

    for (int w = 0; w < 3; w++) {
        const int j = n - 1 + w;
        if (j < 0 || j >= NB) continue;  // padded window: handled analytically in rowsum
        const float* ksrc = x + (size_t)(b * SS + j * 128) * EE;
        float* Lbase = g_probs + (size_t)bn * (BLK * CTX) + w * 128;

        float c[2][8][4];
#pragma unroll
        for (int i = 0; i < 2; i++)
#pragma unroll
            for (int jq = 0; jq < 8; jq++)
#pragma unroll
                for (int t = 0; t < 4; t++) c[i][jq][t] = 0.f;

        StageCvt sb;
        ldg_cvt(sb, ksrc, EE, tid);
        sts_cvt(sb, bbuf[0], bbuf[0] + 10240, tid);
        __syncthreads();
        for (int kc = 0; kc < 8; kc++) {
            int cur = kc & 1, nxt = cur ^ 1;
            if (kc < 7) ldg_cvt(sb, ksrc + (kc + 1) * 32, EE, tid);
            mma_chunkA(uA, kc * 64, ub[cur], lane, m_warp, n_warp, c);
            if (kc < 7) sts_cvt(sb, bbuf[nxt], bbuf[nxt] + 10240, tid);
            __syncthreads();
        }
#pragma unroll
        for (int mi = 0; mi < 2; mi++)
#pragma unroll
            for (int nj = 0; nj < 8; nj++) {
                int r = m_warp + mi * 16 + (lane >> 2);
                int col = n_warp + nj * 8 + (lane & 3) * 2;
                float e0 = __expf(c[mi][nj][0]);
                float e1 = __expf(c[mi][nj][1]);
                float e2 = __expf(c[mi][nj][2]);
                float e3 = __expf(c[mi][nj][3]);
                *(float2*)(Lbase + (size_t)r * CTX + col) = make_float2(e0, e1);
                *(float2*)(Lbase + (size_t)(r + 8) * CTX + col) = make_float2(e2, e3);
                sacc[mi * 2 + 0] += e0 + e1;
                sacc[mi * 2 + 1] += e2 + e3;
            }
        __syncthreads();
    }

    // reduce row sums across lane quads (cols within warp)
#pragma unroll
    for (int k = 0; k < 4; k++) {
        sacc[k] += __shfl_xor_sync(0xFFFFFFFFu, sacc[k], 1);
        sacc[k] += __shfl_xor_sync(0xFFFFFFFFu, sacc[k], 2);
    }
    // exchange between the n-split warp pair via smem (overlay onto B region)
    float* sred = (float*)(dsm + B_PIPE);
    const int g = lane >> 2;
    if ((wid & 1) == 1 && (lane & 3) == 0) {
        sred[m_warp + g] = sacc[0];
        sred[m_warp + g + 8] = sacc[1];
        sred[m_warp + g + 16] = sacc[2];
        sred[m_warp + g + 24] = sacc[3];
    }
    __syncthreads();
    if ((wid & 1) == 0 && (lane & 3) == 0) {
        const float pad = 128.f * (float)((n == 0) + (n == NB - 1));
        int rows[4] = {m_warp + g, m_warp + g + 8, m_warp + g + 16, m_warp + g + 24};
#pragma unroll
        for (int k = 0; k < 4; k++) {
            float tot = sacc[k] + sred[rows[k]] + pad;
            g_rinv[bn * 128 + rows[k]] = 1.f / tot;
        }
    }
}

// ---------------- AV+out: (probs @ uc) * rinv + bo -> d_out (permuted rows). grid (640,2) ----------------
__global__ __launch_bounds__(256) void avo_mma(const float* __restrict__ bo,
                                               float* __restrict__ out) {
    extern __shared__ __align__(16) char dsm[];
    const int tid = threadIdx.x, lane = tid & 31, wid = tid >> 5;
    const int m_warp = (wid >> 1) * 32, n_warp = (wid & 1) * 64;
    const int bn = blockIdx.x;
    const int b = bn >> 5, n = bn & 31;
    const int n0 = blockIdx.y * 128;
    const float* psrc = g_probs + (size_t)bn * (BLK * CTX);
    const float* vsrc = g_uT + (size_t)b * EE * SS + (size_t)n0 * SS;
    char* buf[2] = {dsm, dsm + BUF_SZ};
    const uint32_t ub[2] = {smem_u32(buf[0]), smem_u32(buf[1])};

    int kcs[12], nk = 0;
#pragma unroll
    for (int kc = 0; kc < 12; kc++) {
        int key0 = (n - 1) * 128 + kc * 32;
        if (key0 >= 0 && key0 < SS) kcs[nk++] = kc;
    }

    float c[2][8][4];
#pragma unroll
    for (int i = 0; i < 2; i++)
#pragma unroll
        for (int jq = 0; jq < 8; jq++)
#pragma unroll
            for (int t = 0; t < 4; t++) c[i][jq][t] = 0.f;

    StageCvt sa, sb;
    ldg_cvt(sa, psrc + kcs[0] * 32, CTX, tid);
    ldg_cvt(sb, vsrc + (n - 1) * 128 + kcs[0] * 32, SS, tid);
    sts_cvt(sa, buf[0] + BUF_AH, buf[0] + BUF_AL, tid);
    sts_cvt(sb, buf[0] + BUF_BH, buf[0] + BUF_BL, tid);
    __syncthreads();
    for (int i = 0; i < nk; i++) {
        int cur = i & 1, nxt = cur ^ 1;
        if (i + 1 < nk) {
            ldg_cvt(sa, psrc + kcs[i + 1] * 32, CTX, tid);
            ldg_cvt(sb, vsrc + (n - 1) * 128 + kcs[i + 1] * 32, SS, tid);
        }
        mma_chunk(ub[cur], lane, m_warp, n_warp, c);
        if (i + 1 < nk) {
            sts_cvt(sa, buf[nxt] + BUF_AH, buf[nxt] + BUF_AL, tid);
            sts_cvt(sb, buf[nxt] + BUF_BH, buf[nxt] + BUF_BL, tid);
        }
        __syncthreads();
    }
    const int orow_base = n * (BB * 128) + b * 128;
#pragma unroll
    for (int mi = 0; mi < 2; mi++) {
        int rl = m_warp + mi * 16 + (lane >> 2);
        float ri0 = g_rinv[bn * 128 + rl];
        float ri1 = g_rinv[bn * 128 + rl + 8];
#pragma unroll
        for (int nj = 0; nj < 8; nj++) {
            int r = orow_base + rl;
            int col = n0 + n_warp + nj * 8 + (lane & 3) * 2;
            float2 bv = *(const float2*)(bo + col);
            *(float2*)(out + (size_t)r * EE + col) =
                make_float2(c[mi][nj][0] * ri0 + bv.x, c[mi][nj][1] * ri0 + bv.y);
            *(float2*)(out + (size_t)(r + 8) * EE + col) =
                make_float2(c[mi][nj][2] * ri1 + bv.x, c[mi][nj][3] * ri1 + bv.y);
        }
    }
}

// ---------------- launch ----------------
extern "C" void kernel_launch(void* const* d_in, const int* in_sizes, int n_in,
                              void* d_out, int out_size) {
    const float* x  = (const float*)d_in[0];
    const float* Wq = (const float*)d_in[1];
    const float* Wk = (const float*)d_in[2];
    const float* Wv = (const float*)d_in[3];
    const float* Wo = (const float*)d_in[4];
    const float* bo = (const float*)d_in[5];
    float* out = (float*)d_out;

    static bool attr_done = false;
    if (!attr_done) {
        cudaFuncSetAttribute(proj_full, cudaFuncAttributeMaxDynamicSharedMemorySize, SMEM_FULL);
        cudaFuncSetAttribute(logits_full, cudaFuncAttributeMaxDynamicSharedMemorySize,
                             SMEM_FULL);
        cudaFuncSetAttribute(avo_mma, cudaFuncAttributeMaxDynamicSharedMemorySize, SMEM_PIPE);
        attr_done = true;
    }

    prep_mu_gemm<<<8, 256>>>(Wq, Wk, Wv, Wo);
    proj_full<<<640, 256, SMEM_FULL>>>(x);
    logits_full<<<640, 256, SMEM_FULL>>>(x);
    avo_mma<<<dim3(640, 2), 256, SMEM_PIPE>>>(bo, out);
}